// round 16
// baseline (speedup 1.0000x reference)
#include <cuda_runtime.h>
#include <math.h>
#include <stdint.h>

#define D     256
#define D3    768
#define NTOK  50000
#define NSRL  20000
#define NENT  10000
#define TLEN  50000
#define ETS   300000
#define EEE   150000
#define EST   300000
#define EET   150000

#define TK        32
#define SMEM_PAD  36
#define GEMM_SMEM (2 * 2 * 128 * SMEM_PAD * 4)

// ---------------- scratch ----------------
__device__ float g_Wbig_tok[2048*D];
__device__ float g_bbig_tok[2048];
__device__ float g_Wbig_ent[768*D];
__device__ float g_bbig_ent[768];
__device__ float g_Wbig_rel[512*D];
__device__ float g_big_tok [(size_t)NTOK*2048];   // tok_p | a_tok | gh_tok | gi_feat
__device__ float g_a_srl   [NSRL*D];
__device__ float g_big_ent [NENT*768];            // a_ent | entc | enta
__device__ float g_bertW   [(size_t)TLEN*512];
__device__ float g_Q       [(size_t)(TLEN+1)*512];
__device__ float g_csum    [256*512];
__device__ float g_gi      [(NSRL+NENT)*D3];
__device__ float g_hst     [NTOK*D];
__device__ float g_het     [NTOK*D];
__device__ float g_gA      [NTOK*D3];
__device__ float g_gB      [NTOK*D3];
__device__ float g_h1      [NTOK*D];
__device__ int g_idx_ts[ETS];
__device__ int g_idx_ee[EEE];
__device__ int g_idx_st[EST];
__device__ int g_idx_et[EET];
__device__ int g_cnt   [NSRL + NENT + 2 * NTOK];

__device__ __forceinline__ float rna32(float f) {
    unsigned r;
    asm("cvt.rna.tf32.f32 %0, %1;" : "=r"(r) : "f"(f));
    return __uint_as_float(r);
}
__device__ __forceinline__ unsigned f2tf32(float f) {
    unsigned r;
    asm("cvt.rna.tf32.f32 %0, %1;" : "=r"(r) : "f"(f));
    return r;
}

// ---------------- pack Wbt/bbt (weights RNA-rounded to tf32) ---------------
__global__ void pack_wbt_kernel(const float* __restrict__ Wnt, const float* __restrict__ Whh,
                                const float* __restrict__ Wih, const float* __restrict__ bnt,
                                const float* __restrict__ bhh, const float* __restrict__ bih,
                                float* __restrict__ Wbt, float* __restrict__ bbt) {
    int i = blockIdx.x * blockDim.x + threadIdx.x;
    int stride = gridDim.x * blockDim.x;
    for (int k = i; k < D * D; k += stride)  Wbt[k] = rna32(Wnt[k]);
    for (int k = i; k < D3 * D; k += stride) Wbt[512 * D + k]  = rna32(Whh[k]);
    for (int k = i; k < D3 * D; k += stride) Wbt[1280 * D + k] = rna32(Wih[k]);
    if (i < D)  bbt[i] = bnt[i];
    if (i < D3) { bbt[512 + i] = bhh[i]; bbt[1280 + i] = bih[i]; }
}

// ---------------- batched weight composition (rounded outputs) -------------
struct CJob { const float* L; const float* R; float* out; int ldL, Loff, ldR, Roff, ldo; };
__global__ void compose_mm_batch(CJob a, CJob b, CJob c, CJob d) {
    CJob j = (blockIdx.y == 0) ? a : (blockIdx.y == 1) ? b : (blockIdx.y == 2) ? c : d;
    __shared__ float lrow[D];
    int n = blockIdx.x, k = threadIdx.x;
    lrow[k] = j.L[(size_t)n * j.ldL + j.Loff + k];
    __syncthreads();
    float s[8] = {0.f, 0.f, 0.f, 0.f, 0.f, 0.f, 0.f, 0.f};
#pragma unroll 4
    for (int p = 0; p < D; p += 8) {
#pragma unroll
        for (int u = 0; u < 8; u++)
            s[u] = fmaf(lrow[p + u], j.R[(size_t)(p + u) * j.ldR + j.Roff + k], s[u]);
    }
    j.out[(size_t)n * j.ldo + k] =
        rna32(((s[0] + s[1]) + (s[2] + s[3])) + ((s[4] + s[5]) + (s[6] + s[7])));
}
struct BJob { const float* L; const float* v; const float* base; float* out; int ldL, Loff; };
__global__ void compose_bias_batch(BJob a, BJob b, BJob c) {
    BJob j = (blockIdx.y == 0) ? a : (blockIdx.y == 1) ? b : c;
    int n = blockIdx.x, t = threadIdx.x;
    __shared__ float red[D];
    red[t] = j.L[(size_t)n * j.ldL + j.Loff + t] * j.v[t];
    __syncthreads();
#pragma unroll
    for (int s = 128; s > 0; s >>= 1) {
        if (t < s) red[t] += red[t + s];
        __syncthreads();
    }
    if (t == 0) j.out[n] = red[0] + (j.base ? j.base[n] : 0.0f);
}

// ---------------- TF32 GEMM: A fragments RNA, B raw bits (pre-rounded) -----
__global__ __launch_bounds__(256, 2) void gemm_tf32(
    const float* __restrict__ A, int lda,
    const float* __restrict__ W, int ldw, int koff,
    float* __restrict__ C, int ldc, const float* __restrict__ bias,
    int M, int N)
{
    extern __shared__ float sm[];
    float* Asb = sm;
    float* Bsb = sm + 2 * 128 * SMEM_PAD;
    const int bm = blockIdx.y * 128;
    const int bn = blockIdx.x * 128;
    const int tid = threadIdx.x;
    const int lane = tid & 31;
    const int wid  = tid >> 5;
    const int wm = (wid >> 2) * 64;
    const int wn = (wid & 3)  * 32;
    const int g = lane >> 2;
    const int q = lane & 3;
    const int loadRow = tid >> 3;
    const int loadCol = (tid & 7) * 4;
    const unsigned sA = (unsigned)__cvta_generic_to_shared(Asb);
    const unsigned sB = (unsigned)__cvta_generic_to_shared(Bsb);

    float c[4][4][4];
#pragma unroll
    for (int i = 0; i < 4; i++)
#pragma unroll
        for (int j = 0; j < 4; j++)
#pragma unroll
            for (int k = 0; k < 4; k++) c[i][j][k] = 0.0f;

    auto issue_tile = [&](int t) {
        const int s = t & 1;
        const int k0 = t * TK;
#pragma unroll
        for (int p = 0; p < 4; p++) {
            int r = loadRow + p * 32;
            unsigned da = sA + (unsigned)(((s * 128 + r) * SMEM_PAD + loadCol) * 4);
            int arow = bm + r;
            const float* ga = A + (size_t)(arow < M ? arow : 0) * lda + k0 + loadCol;
            int sz = (arow < M) ? 16 : 0;
            asm volatile("cp.async.ca.shared.global [%0], [%1], 16, %2;\n"
                         :: "r"(da), "l"(ga), "r"(sz));
            unsigned db = sB + (unsigned)(((s * 128 + r) * SMEM_PAD + loadCol) * 4);
            const float* gb = W + (size_t)(bn + r) * ldw + koff + k0 + loadCol;
            asm volatile("cp.async.ca.shared.global [%0], [%1], 16;\n"
                         :: "r"(db), "l"(gb));
        }
        asm volatile("cp.async.commit_group;\n");
    };

    issue_tile(0);
    issue_tile(1);

#pragma unroll
    for (int t = 0; t < 8; t++) {
        if (t < 7) asm volatile("cp.async.wait_group 1;\n");
        else       asm volatile("cp.async.wait_group 0;\n");
        __syncthreads();
        const float* Ab = Asb + (t & 1) * 128 * SMEM_PAD;
        const float* Bb = Bsb + (t & 1) * 128 * SMEM_PAD;
#pragma unroll
        for (int kk = 0; kk < 4; kk++) {
            const int kb = kk * 8;
            unsigned a[4][4], b[4][2];
#pragma unroll
            for (int mt = 0; mt < 4; mt++) {
                int row = wm + mt * 16;
                a[mt][0] = f2tf32(Ab[(row + g    ) * SMEM_PAD + kb + q    ]);
                a[mt][1] = f2tf32(Ab[(row + g + 8) * SMEM_PAD + kb + q    ]);
                a[mt][2] = f2tf32(Ab[(row + g    ) * SMEM_PAD + kb + q + 4]);
                a[mt][3] = f2tf32(Ab[(row + g + 8) * SMEM_PAD + kb + q + 4]);
            }
#pragma unroll
            for (int nt = 0; nt < 4; nt++) {
                int col = wn + nt * 8;
                b[nt][0] = __float_as_uint(Bb[(col + g) * SMEM_PAD + kb + q    ]);
                b[nt][1] = __float_as_uint(Bb[(col + g) * SMEM_PAD + kb + q + 4]);
            }
#pragma unroll
            for (int mt = 0; mt < 4; mt++)
#pragma unroll
                for (int nt = 0; nt < 4; nt++) {
                    asm volatile(
                        "mma.sync.aligned.m16n8k8.row.col.f32.tf32.tf32.f32 "
                        "{%0,%1,%2,%3}, {%4,%5,%6,%7}, {%8,%9}, {%0,%1,%2,%3};\n"
                        : "+f"(c[mt][nt][0]), "+f"(c[mt][nt][1]),
                          "+f"(c[mt][nt][2]), "+f"(c[mt][nt][3])
                        : "r"(a[mt][0]), "r"(a[mt][1]), "r"(a[mt][2]), "r"(a[mt][3]),
                          "r"(b[nt][0]), "r"(b[nt][1]));
                }
        }
        __syncthreads();
        if (t < 6) issue_tile(t + 2);
    }

#pragma unroll
    for (int mt = 0; mt < 4; mt++) {
#pragma unroll
        for (int nt = 0; nt < 4; nt++) {
            int row0 = bm + wm + mt * 16 + g;
            int col  = bn + wn + nt * 8 + q * 2;
            float bx = bias ? bias[col]     : 0.0f;
            float by = bias ? bias[col + 1] : 0.0f;
            if (row0 < M) {
                float2 o; o.x = c[mt][nt][0] + bx; o.y = c[mt][nt][1] + by;
                *(float2*)&C[(size_t)row0 * ldc + col] = o;
            }
            if (row0 + 8 < M) {
                float2 o; o.x = c[mt][nt][2] + bx; o.y = c[mt][nt][3] + by;
                *(float2*)&C[(size_t)(row0 + 8) * ldc + col] = o;
            }
        }
    }
}

// ---------------- fused CSR build ----------------
__global__ void build_csr4_kernel(
    const int* __restrict__ d0, int* __restrict__ i0, int* __restrict__ c0, int deg0,
    const int* __restrict__ d1, int* __restrict__ i1, int* __restrict__ c1, int deg1,
    const int* __restrict__ d2, int* __restrict__ i2, int* __restrict__ c2, int deg2,
    const int* __restrict__ d3, int* __restrict__ i3, int* __restrict__ c3, int deg3)
{
    int e = blockIdx.x * blockDim.x + threadIdx.x;
    if (e < ETS) {
        int d = d0[e];
        int off = atomicAdd(&c0[d], 1);
        if (off < deg0) i0[d * deg0 + off] = e;
    }
    int e1 = e - ETS;
    if (e1 >= 0 && e1 < EEE) {
        int d = d1[e1];
        int off = atomicAdd(&c1[d], 1);
        if (off < deg1) i1[d * deg1 + off] = e1;
    }
    int e2 = e - ETS - EEE;
    if (e2 >= 0 && e2 < EST) {
        int d = d2[e2];
        int off = atomicAdd(&c2[d], 1);
        if (off < deg2) i2[d * deg2 + off] = e2;
    }
    int e3 = e - ETS - EEE - EST;
    if (e3 >= 0 && e3 < EET) {
        int d = d3[e3];
        int off = atomicAdd(&c3[d], 1);
        if (off < deg3) i3[d * deg3 + off] = e3;
    }
}
__global__ void fill_int_kernel(int* __restrict__ p, int n) {
    int i = blockIdx.x * blockDim.x + threadIdx.x;
    for (; i < n; i += gridDim.x * blockDim.x) p[i] = 0;
}

// ---------------- softmax / cumsum / GRU ----------------
__global__ void seg_softmax_agg_kernel(
    const float* __restrict__ a_u, int ldu, const float* __restrict__ a_d, int ldd,
    const float* __restrict__ us, int ldus, const int* __restrict__ src,
    const int* __restrict__ idx, int deg, float* __restrict__ out)
{
    int d = blockIdx.x, c = threadIdx.x;
    float vd = a_d[(size_t)d * ldd + c];
    float den = 0.0f, num = 0.0f;
    for (int i = 0; i < deg; i++) {
        int e = idx[d * deg + i];
        int s = src ? src[e] : e;
        float v = a_u[(size_t)s * ldu + c] + vd;
        v = (v >= 0.0f) ? v : 0.01f * v;
        float ex = __expf(v);
        den += ex;
        num += ex * us[(size_t)s * ldus + c];
    }
    out[(size_t)d * D + c] = num / fmaxf(den, 1e-9f);
}
__global__ void seg_softmax_ee_kernel(
    const float* __restrict__ Q, const int* __restrict__ span,
    const float* __restrict__ rt, const float* __restrict__ big_ent,
    const int* __restrict__ src, const int* __restrict__ idx, int deg,
    float* __restrict__ out)
{
    int d = blockIdx.x, c = threadIdx.x;
    float vd = big_ent[(size_t)d * 768 + c];          // a_ent
    float den = 0.0f, num = 0.0f;
    for (int i = 0; i < deg; i++) {
        int e = idx[d * deg + i];
        int s = src[e];
        int x = span[2 * e], y = span[2 * e + 1];
        float w = rt[e] / (float)(y - x);
        float mee = w * (Q[(size_t)y * 512 + c]       - Q[(size_t)x * 512 + c])
                  + big_ent[(size_t)s * 768 + 256 + c];
        float am  = w * (Q[(size_t)y * 512 + 256 + c] - Q[(size_t)x * 512 + 256 + c])
                  + big_ent[(size_t)s * 768 + 512 + c];
        float v = am + vd;
        v = (v >= 0.0f) ? v : 0.01f * v;
        float ex = __expf(v);
        den += ex;
        num += ex * mee;
    }
    out[(size_t)d * D + c] = num / fmaxf(den, 1e-9f);
}
#define CSCH 256
__global__ void cs_chunk(const float* __restrict__ x, float* __restrict__ csum) {
    int b = blockIdx.x, c = threadIdx.x, C = blockDim.x;
    int r0 = b * CSCH, r1 = min(r0 + CSCH, TLEN);
    float s = 0.0f;
    for (int r = r0; r < r1; r++) s += x[(size_t)r * C + c];
    csum[b * C + c] = s;
}
__global__ void cs_scan(float* __restrict__ csum, int nch, int C) {
    int c = blockIdx.x * blockDim.x + threadIdx.x;
    float run = 0.0f;
    int b = 0;
    for (; b + 8 <= nch; b += 8) {
        float v[8];
#pragma unroll
        for (int i = 0; i < 8; i++) v[i] = csum[(b + i) * C + c];
#pragma unroll
        for (int i = 0; i < 8; i++) { csum[(b + i) * C + c] = run; run += v[i]; }
    }
    for (; b < nch; b++) { float t = csum[b * C + c]; csum[b * C + c] = run; run += t; }
}
__global__ void cs_write(const float* __restrict__ x, const float* __restrict__ csum,
                         float* __restrict__ Q) {
    int b = blockIdx.x, c = threadIdx.x, C = blockDim.x;
    float run = csum[b * C + c];
    if (b == 0) Q[c] = 0.0f;
    int r0 = b * CSCH, r1 = min(r0 + CSCH, TLEN);
    for (int r = r0; r < r1; r++) {
        run += x[(size_t)r * C + c];
        Q[(size_t)(r + 1) * C + c] = run;
    }
}
__device__ __forceinline__ float sigf(float x) { return 1.0f / (1.0f + __expf(-x)); }
__global__ void gru_agg2_kernel(
    const float* __restrict__ gi_srl, const float* __restrict__ gi_ent,
    const float* __restrict__ gh, int ldgh, const float* __restrict__ hmat,
    const int* __restrict__ src_st, const int* __restrict__ idx_st, int deg_st,
    const int* __restrict__ src_et, const int* __restrict__ idx_et, int deg_et,
    float* __restrict__ hst, float* __restrict__ het)
{
    int d = blockIdx.x, c = threadIdx.x;
    float hr = gh[(size_t)d * ldgh + c];
    float hz = gh[(size_t)d * ldgh + D + c];
    float hn = gh[(size_t)d * ldgh + 2 * D + c];
    float h  = hmat[(size_t)d * D + c];
    float acc1 = 0.0f;
    for (int i = 0; i < deg_st; i++) {
        int s = src_st[idx_st[d * deg_st + i]];
        float r  = sigf(gi_srl[(size_t)s * D3 + c] + hr);
        float z  = sigf(gi_srl[(size_t)s * D3 + D + c] + hz);
        float nn = tanhf(gi_srl[(size_t)s * D3 + 2 * D + c] + r * hn);
        acc1 += (1.0f - z) * nn + z * h;
    }
    float acc2 = 0.0f;
    for (int i = 0; i < deg_et; i++) {
        int s = src_et[idx_et[d * deg_et + i]];
        float r  = sigf(gi_ent[(size_t)s * D3 + c] + hr);
        float z  = sigf(gi_ent[(size_t)s * D3 + D + c] + hz);
        float nn = tanhf(gi_ent[(size_t)s * D3 + 2 * D + c] + r * hn);
        acc2 += (1.0f - z) * nn + z * h;
    }
    hst[(size_t)d * D + c] = acc1;
    het[(size_t)d * D + c] = acc2;
}
__global__ void gru_dense_kernel(
    const float* __restrict__ gi, int ldgi, const float* __restrict__ gh,
    const float* __restrict__ hmat, float* __restrict__ out)
{
    size_t i = blockIdx.x;
    int c = threadIdx.x;
    float r  = sigf(gi[i * ldgi + c] + gh[i * D3 + c]);
    float z  = sigf(gi[i * ldgi + D + c] + gh[i * D3 + D + c]);
    float nn = tanhf(gi[i * ldgi + 2 * D + c] + r * gh[i * D3 + 2 * D + c]);
    out[i * D + c] = (1.0f - z) * nn + z * hmat[i * D + c];
}

// ---------------- host ----------------
static inline dim3 ggrid(int M, int N) { return dim3(N / 128, (M + 127) / 128); }
#define GEMM(A, lda, W, ldw, koff, C, ldc, bias, M, N) \
    gemm_tf32<<<ggrid(M, N), 256, GEMM_SMEM>>>(A, lda, W, ldw, koff, C, ldc, bias, M, N)

extern "C" void kernel_launch(void* const* d_in, const int* in_sizes, int n_in,
                              void* d_out, int out_size)
{
    cudaFuncSetAttribute(gemm_tf32, cudaFuncAttributeMaxDynamicSharedMemorySize, GEMM_SMEM);

    const float *feat_tok, *feat_srl, *feat_ent, *bert, *rel_type;
    const float *Wnt, *bnt, *Watt, *batt, *Wrt, *brt, *Wc, *bc, *Wih, *Whh, *bih, *bhh;
    const int *src_ts, *dst_ts, *src_ee, *dst_ee, *span, *src_st, *dst_st, *src_et, *dst_et;

    feat_tok = (const float*)d_in[0];
    feat_srl = (const float*)d_in[1];
    feat_ent = (const float*)d_in[2];
    bert     = (const float*)d_in[3];
    rel_type = (const float*)d_in[4];
    if (in_sizes[5] == 65536) {
        Wnt  = (const float*)d_in[5];  bnt  = (const float*)d_in[6];
        Watt = (const float*)d_in[7];  batt = (const float*)d_in[8];
        Wrt  = (const float*)d_in[9];  brt  = (const float*)d_in[10];
        Wc   = (const float*)d_in[11]; bc   = (const float*)d_in[12];
        Wih  = (const float*)d_in[13]; Whh  = (const float*)d_in[14];
        bih  = (const float*)d_in[15]; bhh  = (const float*)d_in[16];
        src_ts = (const int*)d_in[17]; dst_ts = (const int*)d_in[18];
        src_ee = (const int*)d_in[19]; dst_ee = (const int*)d_in[20];
        span   = (const int*)d_in[21];
        src_st = (const int*)d_in[22]; dst_st = (const int*)d_in[23];
        src_et = (const int*)d_in[24]; dst_et = (const int*)d_in[25];
    } else {
        src_ts = (const int*)d_in[5];  dst_ts = (const int*)d_in[6];
        src_ee = (const int*)d_in[7];  dst_ee = (const int*)d_in[8];
        src_st = (const int*)d_in[9];  dst_st = (const int*)d_in[10];
        src_et = (const int*)d_in[11]; dst_et = (const int*)d_in[12];
        span   = (const int*)d_in[13];
        Wnt  = (const float*)d_in[14]; bnt  = (const float*)d_in[15];
        Watt = (const float*)d_in[16]; batt = (const float*)d_in[17];
        Wrt  = (const float*)d_in[18]; brt  = (const float*)d_in[19];
        Wc   = (const float*)d_in[20]; bc   = (const float*)d_in[21];
        Wih  = (const float*)d_in[22]; Whh  = (const float*)d_in[23];
        bih  = (const float*)d_in[24]; bhh  = (const float*)d_in[25];
    }

    float *Wbt, *bbt, *Wbe, *bbe, *Wbr, *big_tok, *a_srl, *big_ent;
    float *bertW, *Q, *csum, *gi, *hst, *het, *gA, *gB, *h1;
    int *idx_ts, *idx_ee, *idx_st, *idx_et, *cnt;
    cudaGetSymbolAddress((void**)&Wbt, g_Wbig_tok);   cudaGetSymbolAddress((void**)&bbt, g_bbig_tok);
    cudaGetSymbolAddress((void**)&Wbe, g_Wbig_ent);   cudaGetSymbolAddress((void**)&bbe, g_bbig_ent);
    cudaGetSymbolAddress((void**)&Wbr, g_Wbig_rel);   cudaGetSymbolAddress((void**)&big_tok, g_big_tok);
    cudaGetSymbolAddress((void**)&a_srl, g_a_srl);    cudaGetSymbolAddress((void**)&big_ent, g_big_ent);
    cudaGetSymbolAddress((void**)&bertW, g_bertW);    cudaGetSymbolAddress((void**)&Q, g_Q);
    cudaGetSymbolAddress((void**)&csum, g_csum);      cudaGetSymbolAddress((void**)&gi, g_gi);
    cudaGetSymbolAddress((void**)&hst, g_hst);        cudaGetSymbolAddress((void**)&het, g_het);
    cudaGetSymbolAddress((void**)&gA, g_gA);          cudaGetSymbolAddress((void**)&gB, g_gB);
    cudaGetSymbolAddress((void**)&h1, g_h1);
    cudaGetSymbolAddress((void**)&idx_ts, g_idx_ts);  cudaGetSymbolAddress((void**)&idx_ee, g_idx_ee);
    cudaGetSymbolAddress((void**)&idx_st, g_idx_st);  cudaGetSymbolAddress((void**)&idx_et, g_idx_et);
    cudaGetSymbolAddress((void**)&cnt, g_cnt);

    float* out   = (float*)d_out;
    float* h_tok = out;
    float* h_srl = out + (size_t)NTOK * D;
    float* h_ent = out + (size_t)(NTOK + NSRL) * D;

    // rounded weight copies inside Wbt
    const float* Whh_r = Wbt + 512 * D;
    const float* Wih_r = Wbt + 1280 * D;

    // 1: pack (weights RNA-rounded)
    pack_wbt_kernel<<<512, 256>>>(Wnt, Whh, Wih, bnt, bhh, bih, Wbt, bbt);
    // 2: phase-1 mm composes (rounded outputs)
    {
        CJob j0 = {Watt, Wnt, Wbt + 256 * D, 2 * D, 0,   D,     0,   D};  // Wa_l@Wnt
        CJob j1 = {Watt, Wnt, Wbe,           2 * D, D,   D,     0,   D};  // Wa_r@Wnt
        CJob j2 = {Wc,   Wrt, Wbe + 256 * D, D,     0,   2 * D, 0,   D};  // Wbe2=Wc@Wrt_l
        CJob j3 = {Wc,   Wrt, Wbr,           D,     0,   2 * D, D,   D};  // W1 =Wc@Wrt_r
        compose_mm_batch<<<dim3(D, 4), D>>>(j0, j1, j2, j3);
    }
    // 3: phase-1 bias composes
    {
        BJob b0 = {Watt, bnt, nullptr, bbt + 256, 2 * D, 0};
        BJob b1 = {Watt, bnt, batt,    bbe,       2 * D, D};
        BJob b2 = {Wc,   brt, bc,      bbe + 256, D,     0};
        compose_bias_batch<<<dim3(D, 3), D>>>(b0, b1, b2);
    }
    // 4: big tok GEMM (ncu profiles this)
    GEMM(feat_tok, D, Wbt, D, 0, big_tok, 2048, bbt, NTOK, 2048);
    // phase-2 composes (note: k0/k1 L-operands read pre-rounded W1/Wbe2 — fine, fp32 math then rounded)
    {
        CJob k0 = {Watt, Wbr,           Wbr + 256 * D, 2 * D, 0, D, 0, D};  // W2 = Wa_l@W1
        CJob k1 = {Watt, Wbe + 256 * D, Wbe + 512 * D, 2 * D, 0, D, 0, D};  // W3 = Wa_l@Wbe2
        compose_mm_batch<<<dim3(D, 2), D>>>(k0, k1, k0, k0);
        BJob c0 = {Watt, bbe + 256, nullptr, bbe + 512, 2 * D, 0};          // Wa_l@b2
        compose_bias_batch<<<dim3(D, 1), D>>>(c0, c0, c0);
    }
    // remaining node GEMMs
    GEMM(feat_srl, D, Wbe, D, 0, a_srl, D, bbe, NSRL, D);
    GEMM(feat_ent, D, Wbe, D, 0, big_ent, 768, bbe, NENT, 768);   // a_ent|entc|enta
    GEMM(bert,     D, Wbr, D, 0, bertW, 512, nullptr, TLEN, 512); // bert@[W1|W2]

    // CSR builds
    int* cnt_ts = cnt;
    int* cnt_ee = cnt + NSRL;
    int* cnt_st = cnt + NSRL + NENT;
    int* cnt_et = cnt + NSRL + NENT + NTOK;
    fill_int_kernel<<<512, 256>>>(cnt, NSRL + NENT + 2 * NTOK);
    build_csr4_kernel<<<(ETS + EEE + EST + EET + 255) / 256, 256>>>(
        dst_ts, idx_ts, cnt_ts, ETS / NSRL,
        dst_ee, idx_ee, cnt_ee, EEE / NENT,
        dst_st, idx_st, cnt_st, EST / NTOK,
        dst_et, idx_et, cnt_et, EET / NTOK);

    // TS segmented softmax -> h_srl
    seg_softmax_agg_kernel<<<NSRL, 256>>>(big_tok + 256, 2048, a_srl, D,
                                          big_tok, 2048, src_ts, idx_ts, ETS / NSRL, h_srl);

    // 512-ch prefix sums -> Q, then fused EE softmax
    const int nch = (TLEN + CSCH - 1) / CSCH;
    cs_chunk<<<nch, 512>>>(bertW, csum);
    cs_scan<<<2, 256>>>(csum, nch, 512);
    cs_write<<<nch, 512>>>(bertW, csum, Q);
    seg_softmax_ee_kernel<<<NENT, 256>>>(Q, span, rel_type, big_ent, src_ee,
                                         idx_ee, EEE / NENT, h_ent);

    // GRU input projections (h_srl & h_ent contiguous in d_out)
    GEMM(h_srl, D, Wih_r, D, 0, gi, D3, bih, NSRL + NENT, D3);
    float* gi_srl = gi;
    float* gi_ent = gi + (size_t)NSRL * D3;

    // merged edge-GRU aggregation
    gru_agg2_kernel<<<NTOK, 256>>>(gi_srl, gi_ent, big_tok + 512, 2048, feat_tok,
                                   src_st, idx_st, EST / NTOK,
                                   src_et, idx_et, EET / NTOK, hst, het);

    GEMM(het, D, Wih_r, D, 0, gA, D3, bih, NTOK, D3);
    GEMM(hst, D, Whh_r, D, 0, gB, D3, bhh, NTOK, D3);
    gru_dense_kernel<<<NTOK, 256>>>(gA, D3, gB, hst, h1);

    GEMM(h1, D, Whh_r, D, 0, gB, D3, bhh, NTOK, D3);
    gru_dense_kernel<<<NTOK, 256>>>(big_tok + 1280, 2048, gB, h1, h_tok);
}

// round 17
// speedup vs baseline: 1.0823x; 1.0823x over previous
#include <cuda_runtime.h>
#include <math.h>
#include <stdint.h>

#define D     256
#define D3    768
#define NTOK  50000
#define NSRL  20000
#define NENT  10000
#define TLEN  50000
#define ETS   300000
#define EEE   150000
#define EST   300000
#define EET   150000

#define TK        32
#define SMEM_PAD  36
#define GEMM_SMEM (2 * 2 * 128 * SMEM_PAD * 4)

// ---------------- scratch ----------------
__device__ float g_Wbig_tok[2048*D];
__device__ float g_bbig_tok[2048];
__device__ float g_Wbig_ent[768*D];
__device__ float g_bbig_ent[768];
__device__ float g_Wbig_rel[512*D];
__device__ float g_big_tok [(size_t)NTOK*2048];   // tok_p | a_tok | gh_tok | gi_feat
__device__ float g_a_srl   [NSRL*D];
__device__ float g_big_ent [NENT*768];            // a_ent | entc | enta
__device__ float g_bertW   [(size_t)TLEN*512];
__device__ float g_Q       [(size_t)(TLEN+1)*512];
__device__ float g_csum    [256*512];
__device__ float g_gi      [(NSRL+NENT)*D3];
__device__ float g_hst     [NTOK*D];
__device__ float g_het     [NTOK*D];
__device__ float g_gA      [NTOK*D3];
__device__ float g_gB      [NTOK*D3];
__device__ float g_h1      [NTOK*D];
__device__ int g_idx_ts[ETS];
__device__ int g_idx_ee[EEE];
__device__ int g_idx_st[EST];
__device__ int g_idx_et[EET];
__device__ int g_cnt   [NSRL + NENT + 2 * NTOK];

__device__ __forceinline__ float rna32(float f) {
    unsigned r;
    asm("cvt.rna.tf32.f32 %0, %1;" : "=r"(r) : "f"(f));
    return __uint_as_float(r);
}
__device__ __forceinline__ unsigned f2tf32(float f) {
    unsigned r;
    asm("cvt.rna.tf32.f32 %0, %1;" : "=r"(r) : "f"(f));
    return r;
}

// ---------------- pack Wbt/bbt (weights RNA-rounded to tf32) ---------------
__global__ void pack_wbt_kernel(const float* __restrict__ Wnt, const float* __restrict__ Whh,
                                const float* __restrict__ Wih, const float* __restrict__ bnt,
                                const float* __restrict__ bhh, const float* __restrict__ bih,
                                float* __restrict__ Wbt, float* __restrict__ bbt) {
    int i = blockIdx.x * blockDim.x + threadIdx.x;
    int stride = gridDim.x * blockDim.x;
    for (int k = i; k < D * D; k += stride)  Wbt[k] = rna32(Wnt[k]);
    for (int k = i; k < D3 * D; k += stride) Wbt[512 * D + k]  = rna32(Whh[k]);
    for (int k = i; k < D3 * D; k += stride) Wbt[1280 * D + k] = rna32(Wih[k]);
    if (i < D)  bbt[i] = bnt[i];
    if (i < D3) { bbt[512 + i] = bhh[i]; bbt[1280 + i] = bih[i]; }
}

// ---------------- batched weight composition (rounded outputs) -------------
struct CJob { const float* L; const float* R; float* out; int ldL, Loff, ldR, Roff, ldo; };
__global__ void compose_mm_batch(CJob a, CJob b, CJob c, CJob d) {
    CJob j = (blockIdx.y == 0) ? a : (blockIdx.y == 1) ? b : (blockIdx.y == 2) ? c : d;
    __shared__ float lrow[D];
    int n = blockIdx.x, k = threadIdx.x;
    lrow[k] = j.L[(size_t)n * j.ldL + j.Loff + k];
    __syncthreads();
    float s[8] = {0.f, 0.f, 0.f, 0.f, 0.f, 0.f, 0.f, 0.f};
#pragma unroll 4
    for (int p = 0; p < D; p += 8) {
#pragma unroll
        for (int u = 0; u < 8; u++)
            s[u] = fmaf(lrow[p + u], j.R[(size_t)(p + u) * j.ldR + j.Roff + k], s[u]);
    }
    j.out[(size_t)n * j.ldo + k] =
        rna32(((s[0] + s[1]) + (s[2] + s[3])) + ((s[4] + s[5]) + (s[6] + s[7])));
}
struct BJob { const float* L; const float* v; const float* base; float* out; int ldL, Loff; };
__global__ void compose_bias_batch(BJob a, BJob b, BJob c) {
    BJob j = (blockIdx.y == 0) ? a : (blockIdx.y == 1) ? b : c;
    int n = blockIdx.x, t = threadIdx.x;
    __shared__ float red[D];
    red[t] = j.L[(size_t)n * j.ldL + j.Loff + t] * j.v[t];
    __syncthreads();
#pragma unroll
    for (int s = 128; s > 0; s >>= 1) {
        if (t < s) red[t] += red[t + s];
        __syncthreads();
    }
    if (t == 0) j.out[n] = red[0] + (j.base ? j.base[n] : 0.0f);
}

// ---------------- TF32 GEMM: A fragments RNA, B raw bits (pre-rounded) -----
__global__ __launch_bounds__(256, 2) void gemm_tf32(
    const float* __restrict__ A, int lda,
    const float* __restrict__ W, int ldw, int koff,
    float* __restrict__ C, int ldc, const float* __restrict__ bias,
    int M, int N)
{
    extern __shared__ float sm[];
    float* Asb = sm;
    float* Bsb = sm + 2 * 128 * SMEM_PAD;
    const int bm = blockIdx.y * 128;
    const int bn = blockIdx.x * 128;
    const int tid = threadIdx.x;
    const int lane = tid & 31;
    const int wid  = tid >> 5;
    const int wm = (wid >> 2) * 64;
    const int wn = (wid & 3)  * 32;
    const int g = lane >> 2;
    const int q = lane & 3;
    const int loadRow = tid >> 3;
    const int loadCol = (tid & 7) * 4;
    const unsigned sA = (unsigned)__cvta_generic_to_shared(Asb);
    const unsigned sB = (unsigned)__cvta_generic_to_shared(Bsb);

    float c[4][4][4];
#pragma unroll
    for (int i = 0; i < 4; i++)
#pragma unroll
        for (int j = 0; j < 4; j++)
#pragma unroll
            for (int k = 0; k < 4; k++) c[i][j][k] = 0.0f;

    auto issue_tile = [&](int t) {
        const int s = t & 1;
        const int k0 = t * TK;
#pragma unroll
        for (int p = 0; p < 4; p++) {
            int r = loadRow + p * 32;
            unsigned da = sA + (unsigned)(((s * 128 + r) * SMEM_PAD + loadCol) * 4);
            int arow = bm + r;
            const float* ga = A + (size_t)(arow < M ? arow : 0) * lda + k0 + loadCol;
            int sz = (arow < M) ? 16 : 0;
            asm volatile("cp.async.ca.shared.global [%0], [%1], 16, %2;\n"
                         :: "r"(da), "l"(ga), "r"(sz));
            unsigned db = sB + (unsigned)(((s * 128 + r) * SMEM_PAD + loadCol) * 4);
            const float* gb = W + (size_t)(bn + r) * ldw + koff + k0 + loadCol;
            asm volatile("cp.async.ca.shared.global [%0], [%1], 16;\n"
                         :: "r"(db), "l"(gb));
        }
        asm volatile("cp.async.commit_group;\n");
    };

    issue_tile(0);
    issue_tile(1);

#pragma unroll
    for (int t = 0; t < 8; t++) {
        if (t < 7) asm volatile("cp.async.wait_group 1;\n");
        else       asm volatile("cp.async.wait_group 0;\n");
        __syncthreads();
        const float* Ab = Asb + (t & 1) * 128 * SMEM_PAD;
        const float* Bb = Bsb + (t & 1) * 128 * SMEM_PAD;
#pragma unroll
        for (int kk = 0; kk < 4; kk++) {
            const int kb = kk * 8;
            unsigned a[4][4], b[4][2];
#pragma unroll
            for (int mt = 0; mt < 4; mt++) {
                int row = wm + mt * 16;
                a[mt][0] = f2tf32(Ab[(row + g    ) * SMEM_PAD + kb + q    ]);
                a[mt][1] = f2tf32(Ab[(row + g + 8) * SMEM_PAD + kb + q    ]);
                a[mt][2] = f2tf32(Ab[(row + g    ) * SMEM_PAD + kb + q + 4]);
                a[mt][3] = f2tf32(Ab[(row + g + 8) * SMEM_PAD + kb + q + 4]);
            }
#pragma unroll
            for (int nt = 0; nt < 4; nt++) {
                int col = wn + nt * 8;
                b[nt][0] = __float_as_uint(Bb[(col + g) * SMEM_PAD + kb + q    ]);
                b[nt][1] = __float_as_uint(Bb[(col + g) * SMEM_PAD + kb + q + 4]);
            }
#pragma unroll
            for (int mt = 0; mt < 4; mt++)
#pragma unroll
                for (int nt = 0; nt < 4; nt++) {
                    asm volatile(
                        "mma.sync.aligned.m16n8k8.row.col.f32.tf32.tf32.f32 "
                        "{%0,%1,%2,%3}, {%4,%5,%6,%7}, {%8,%9}, {%0,%1,%2,%3};\n"
                        : "+f"(c[mt][nt][0]), "+f"(c[mt][nt][1]),
                          "+f"(c[mt][nt][2]), "+f"(c[mt][nt][3])
                        : "r"(a[mt][0]), "r"(a[mt][1]), "r"(a[mt][2]), "r"(a[mt][3]),
                          "r"(b[nt][0]), "r"(b[nt][1]));
                }
        }
        __syncthreads();
        if (t < 6) issue_tile(t + 2);
    }

#pragma unroll
    for (int mt = 0; mt < 4; mt++) {
#pragma unroll
        for (int nt = 0; nt < 4; nt++) {
            int row0 = bm + wm + mt * 16 + g;
            int col  = bn + wn + nt * 8 + q * 2;
            float bx = bias ? bias[col]     : 0.0f;
            float by = bias ? bias[col + 1] : 0.0f;
            if (row0 < M) {
                float2 o; o.x = c[mt][nt][0] + bx; o.y = c[mt][nt][1] + by;
                *(float2*)&C[(size_t)row0 * ldc + col] = o;
            }
            if (row0 + 8 < M) {
                float2 o; o.x = c[mt][nt][2] + bx; o.y = c[mt][nt][3] + by;
                *(float2*)&C[(size_t)(row0 + 8) * ldc + col] = o;
            }
        }
    }
}

// ---------------- fused CSR build ----------------
__global__ void build_csr4_kernel(
    const int* __restrict__ d0, int* __restrict__ i0, int* __restrict__ c0, int deg0,
    const int* __restrict__ d1, int* __restrict__ i1, int* __restrict__ c1, int deg1,
    const int* __restrict__ d2, int* __restrict__ i2, int* __restrict__ c2, int deg2,
    const int* __restrict__ d3, int* __restrict__ i3, int* __restrict__ c3, int deg3)
{
    int e = blockIdx.x * blockDim.x + threadIdx.x;
    if (e < ETS) {
        int d = d0[e];
        int off = atomicAdd(&c0[d], 1);
        if (off < deg0) i0[d * deg0 + off] = e;
    }
    int e1 = e - ETS;
    if (e1 >= 0 && e1 < EEE) {
        int d = d1[e1];
        int off = atomicAdd(&c1[d], 1);
        if (off < deg1) i1[d * deg1 + off] = e1;
    }
    int e2 = e - ETS - EEE;
    if (e2 >= 0 && e2 < EST) {
        int d = d2[e2];
        int off = atomicAdd(&c2[d], 1);
        if (off < deg2) i2[d * deg2 + off] = e2;
    }
    int e3 = e - ETS - EEE - EST;
    if (e3 >= 0 && e3 < EET) {
        int d = d3[e3];
        int off = atomicAdd(&c3[d], 1);
        if (off < deg3) i3[d * deg3 + off] = e3;
    }
}
__global__ void fill_int_kernel(int* __restrict__ p, int n) {
    int i = blockIdx.x * blockDim.x + threadIdx.x;
    for (; i < n; i += gridDim.x * blockDim.x) p[i] = 0;
}

// ---------------- softmax / cumsum / GRU (DEG compile-time -> full MLP) ----
template<int DEG>
__global__ void seg_softmax_agg_kernel(
    const float* __restrict__ a_u, int ldu, const float* __restrict__ a_d, int ldd,
    const float* __restrict__ us, int ldus, const int* __restrict__ src,
    const int* __restrict__ idx, float* __restrict__ out)
{
    int d = blockIdx.x, c = threadIdx.x;
    int sidx[DEG];
#pragma unroll
    for (int i = 0; i < DEG; i++) {
        int e = idx[d * DEG + i];
        sidx[i] = src ? src[e] : e;
    }
    float vd = a_d[(size_t)d * ldd + c];
    float den = 0.0f, num = 0.0f;
#pragma unroll
    for (int i = 0; i < DEG; i++) {
        int s = sidx[i];
        float v = a_u[(size_t)s * ldu + c] + vd;
        v = (v >= 0.0f) ? v : 0.01f * v;
        float ex = __expf(v);
        den += ex;
        num += ex * us[(size_t)s * ldus + c];
    }
    out[(size_t)d * D + c] = num / fmaxf(den, 1e-9f);
}

template<int DEG>
__global__ void seg_softmax_ee_kernel(
    const float* __restrict__ Q, const int* __restrict__ span,
    const float* __restrict__ rt, const float* __restrict__ big_ent,
    const int* __restrict__ src, const int* __restrict__ idx,
    float* __restrict__ out)
{
    int d = blockIdx.x, c = threadIdx.x;
    int sv[DEG], xv[DEG], yv[DEG];
    float wv[DEG];
#pragma unroll
    for (int i = 0; i < DEG; i++) {
        int e = idx[d * DEG + i];
        sv[i] = src[e];
        xv[i] = span[2 * e];
        yv[i] = span[2 * e + 1];
        wv[i] = rt[e];
    }
    float vd = big_ent[(size_t)d * 768 + c];          // a_ent
    float den = 0.0f, num = 0.0f;
#pragma unroll
    for (int i = 0; i < DEG; i++) {
        int s = sv[i], x = xv[i], y = yv[i];
        float w = wv[i] / (float)(y - x);
        float mee = w * (Q[(size_t)y * 512 + c]       - Q[(size_t)x * 512 + c])
                  + big_ent[(size_t)s * 768 + 256 + c];
        float am  = w * (Q[(size_t)y * 512 + 256 + c] - Q[(size_t)x * 512 + 256 + c])
                  + big_ent[(size_t)s * 768 + 512 + c];
        float v = am + vd;
        v = (v >= 0.0f) ? v : 0.01f * v;
        float ex = __expf(v);
        den += ex;
        num += ex * mee;
    }
    out[(size_t)d * D + c] = num / fmaxf(den, 1e-9f);
}

#define CSCH 256
__global__ void cs_chunk(const float* __restrict__ x, float* __restrict__ csum) {
    int b = blockIdx.x, c = threadIdx.x, C = blockDim.x;
    int r0 = b * CSCH, r1 = min(r0 + CSCH, TLEN);
    float s = 0.0f;
    for (int r = r0; r < r1; r++) s += x[(size_t)r * C + c];
    csum[b * C + c] = s;
}
__global__ void cs_scan(float* __restrict__ csum, int nch, int C) {
    int c = blockIdx.x * blockDim.x + threadIdx.x;
    float run = 0.0f;
    int b = 0;
    for (; b + 8 <= nch; b += 8) {
        float v[8];
#pragma unroll
        for (int i = 0; i < 8; i++) v[i] = csum[(b + i) * C + c];
#pragma unroll
        for (int i = 0; i < 8; i++) { csum[(b + i) * C + c] = run; run += v[i]; }
    }
    for (; b < nch; b++) { float t = csum[b * C + c]; csum[b * C + c] = run; run += t; }
}
__global__ void cs_write(const float* __restrict__ x, const float* __restrict__ csum,
                         float* __restrict__ Q) {
    int b = blockIdx.x, c = threadIdx.x, C = blockDim.x;
    float run = csum[b * C + c];
    if (b == 0) Q[c] = 0.0f;
    int r0 = b * CSCH, r1 = min(r0 + CSCH, TLEN);
    for (int r = r0; r < r1; r++) {
        run += x[(size_t)r * C + c];
        Q[(size_t)(r + 1) * C + c] = run;
    }
}
__device__ __forceinline__ float sigf(float x) { return 1.0f / (1.0f + __expf(-x)); }

template<int DEG1, int DEG2>
__global__ void gru_agg2_kernel(
    const float* __restrict__ gi_srl, const float* __restrict__ gi_ent,
    const float* __restrict__ gh, int ldgh, const float* __restrict__ hmat,
    const int* __restrict__ src_st, const int* __restrict__ idx_st,
    const int* __restrict__ src_et, const int* __restrict__ idx_et,
    float* __restrict__ hst, float* __restrict__ het)
{
    int d = blockIdx.x, c = threadIdx.x;
    int s1[DEG1], s2[DEG2];
#pragma unroll
    for (int i = 0; i < DEG1; i++) s1[i] = src_st[idx_st[d * DEG1 + i]];
#pragma unroll
    for (int i = 0; i < DEG2; i++) s2[i] = src_et[idx_et[d * DEG2 + i]];
    float hr = gh[(size_t)d * ldgh + c];
    float hz = gh[(size_t)d * ldgh + D + c];
    float hn = gh[(size_t)d * ldgh + 2 * D + c];
    float h  = hmat[(size_t)d * D + c];
    float acc1 = 0.0f;
#pragma unroll
    for (int i = 0; i < DEG1; i++) {
        int s = s1[i];
        float r  = sigf(gi_srl[(size_t)s * D3 + c] + hr);
        float z  = sigf(gi_srl[(size_t)s * D3 + D + c] + hz);
        float nn = tanhf(gi_srl[(size_t)s * D3 + 2 * D + c] + r * hn);
        acc1 += (1.0f - z) * nn + z * h;
    }
    float acc2 = 0.0f;
#pragma unroll
    for (int i = 0; i < DEG2; i++) {
        int s = s2[i];
        float r  = sigf(gi_ent[(size_t)s * D3 + c] + hr);
        float z  = sigf(gi_ent[(size_t)s * D3 + D + c] + hz);
        float nn = tanhf(gi_ent[(size_t)s * D3 + 2 * D + c] + r * hn);
        acc2 += (1.0f - z) * nn + z * h;
    }
    hst[(size_t)d * D + c] = acc1;
    het[(size_t)d * D + c] = acc2;
}
__global__ void gru_dense_kernel(
    const float* __restrict__ gi, int ldgi, const float* __restrict__ gh,
    const float* __restrict__ hmat, float* __restrict__ out)
{
    size_t i = blockIdx.x;
    int c = threadIdx.x;
    float r  = sigf(gi[i * ldgi + c] + gh[i * D3 + c]);
    float z  = sigf(gi[i * ldgi + D + c] + gh[i * D3 + D + c]);
    float nn = tanhf(gi[i * ldgi + 2 * D + c] + r * gh[i * D3 + 2 * D + c]);
    out[i * D + c] = (1.0f - z) * nn + z * hmat[i * D + c];
}

// ---------------- host ----------------
static inline dim3 ggrid(int M, int N) { return dim3(N / 128, (M + 127) / 128); }
#define GEMM(A, lda, W, ldw, koff, C, ldc, bias, M, N) \
    gemm_tf32<<<ggrid(M, N), 256, GEMM_SMEM>>>(A, lda, W, ldw, koff, C, ldc, bias, M, N)

extern "C" void kernel_launch(void* const* d_in, const int* in_sizes, int n_in,
                              void* d_out, int out_size)
{
    cudaFuncSetAttribute(gemm_tf32, cudaFuncAttributeMaxDynamicSharedMemorySize, GEMM_SMEM);

    const float *feat_tok, *feat_srl, *feat_ent, *bert, *rel_type;
    const float *Wnt, *bnt, *Watt, *batt, *Wrt, *brt, *Wc, *bc, *Wih, *Whh, *bih, *bhh;
    const int *src_ts, *dst_ts, *src_ee, *dst_ee, *span, *src_st, *dst_st, *src_et, *dst_et;

    feat_tok = (const float*)d_in[0];
    feat_srl = (const float*)d_in[1];
    feat_ent = (const float*)d_in[2];
    bert     = (const float*)d_in[3];
    rel_type = (const float*)d_in[4];
    if (in_sizes[5] == 65536) {
        Wnt  = (const float*)d_in[5];  bnt  = (const float*)d_in[6];
        Watt = (const float*)d_in[7];  batt = (const float*)d_in[8];
        Wrt  = (const float*)d_in[9];  brt  = (const float*)d_in[10];
        Wc   = (const float*)d_in[11]; bc   = (const float*)d_in[12];
        Wih  = (const float*)d_in[13]; Whh  = (const float*)d_in[14];
        bih  = (const float*)d_in[15]; bhh  = (const float*)d_in[16];
        src_ts = (const int*)d_in[17]; dst_ts = (const int*)d_in[18];
        src_ee = (const int*)d_in[19]; dst_ee = (const int*)d_in[20];
        span   = (const int*)d_in[21];
        src_st = (const int*)d_in[22]; dst_st = (const int*)d_in[23];
        src_et = (const int*)d_in[24]; dst_et = (const int*)d_in[25];
    } else {
        src_ts = (const int*)d_in[5];  dst_ts = (const int*)d_in[6];
        src_ee = (const int*)d_in[7];  dst_ee = (const int*)d_in[8];
        src_st = (const int*)d_in[9];  dst_st = (const int*)d_in[10];
        src_et = (const int*)d_in[11]; dst_et = (const int*)d_in[12];
        span   = (const int*)d_in[13];
        Wnt  = (const float*)d_in[14]; bnt  = (const float*)d_in[15];
        Watt = (const float*)d_in[16]; batt = (const float*)d_in[17];
        Wrt  = (const float*)d_in[18]; brt  = (const float*)d_in[19];
        Wc   = (const float*)d_in[20]; bc   = (const float*)d_in[21];
        Wih  = (const float*)d_in[22]; Whh  = (const float*)d_in[23];
        bih  = (const float*)d_in[24]; bhh  = (const float*)d_in[25];
    }

    float *Wbt, *bbt, *Wbe, *bbe, *Wbr, *big_tok, *a_srl, *big_ent;
    float *bertW, *Q, *csum, *gi, *hst, *het, *gA, *gB, *h1;
    int *idx_ts, *idx_ee, *idx_st, *idx_et, *cnt;
    cudaGetSymbolAddress((void**)&Wbt, g_Wbig_tok);   cudaGetSymbolAddress((void**)&bbt, g_bbig_tok);
    cudaGetSymbolAddress((void**)&Wbe, g_Wbig_ent);   cudaGetSymbolAddress((void**)&bbe, g_bbig_ent);
    cudaGetSymbolAddress((void**)&Wbr, g_Wbig_rel);   cudaGetSymbolAddress((void**)&big_tok, g_big_tok);
    cudaGetSymbolAddress((void**)&a_srl, g_a_srl);    cudaGetSymbolAddress((void**)&big_ent, g_big_ent);
    cudaGetSymbolAddress((void**)&bertW, g_bertW);    cudaGetSymbolAddress((void**)&Q, g_Q);
    cudaGetSymbolAddress((void**)&csum, g_csum);      cudaGetSymbolAddress((void**)&gi, g_gi);
    cudaGetSymbolAddress((void**)&hst, g_hst);        cudaGetSymbolAddress((void**)&het, g_het);
    cudaGetSymbolAddress((void**)&gA, g_gA);          cudaGetSymbolAddress((void**)&gB, g_gB);
    cudaGetSymbolAddress((void**)&h1, g_h1);
    cudaGetSymbolAddress((void**)&idx_ts, g_idx_ts);  cudaGetSymbolAddress((void**)&idx_ee, g_idx_ee);
    cudaGetSymbolAddress((void**)&idx_st, g_idx_st);  cudaGetSymbolAddress((void**)&idx_et, g_idx_et);
    cudaGetSymbolAddress((void**)&cnt, g_cnt);

    float* out   = (float*)d_out;
    float* h_tok = out;
    float* h_srl = out + (size_t)NTOK * D;
    float* h_ent = out + (size_t)(NTOK + NSRL) * D;

    const float* Whh_r = Wbt + 512 * D;
    const float* Wih_r = Wbt + 1280 * D;

    // 1: pack (weights RNA-rounded)
    pack_wbt_kernel<<<512, 256>>>(Wnt, Whh, Wih, bnt, bhh, bih, Wbt, bbt);
    // 2: phase-1 mm composes
    {
        CJob j0 = {Watt, Wnt, Wbt + 256 * D, 2 * D, 0,   D,     0,   D};
        CJob j1 = {Watt, Wnt, Wbe,           2 * D, D,   D,     0,   D};
        CJob j2 = {Wc,   Wrt, Wbe + 256 * D, D,     0,   2 * D, 0,   D};
        CJob j3 = {Wc,   Wrt, Wbr,           D,     0,   2 * D, D,   D};
        compose_mm_batch<<<dim3(D, 4), D>>>(j0, j1, j2, j3);
    }
    // 3: phase-1 bias composes
    {
        BJob b0 = {Watt, bnt, nullptr, bbt + 256, 2 * D, 0};
        BJob b1 = {Watt, bnt, batt,    bbe,       2 * D, D};
        BJob b2 = {Wc,   brt, bc,      bbe + 256, D,     0};
        compose_bias_batch<<<dim3(D, 3), D>>>(b0, b1, b2);
    }
    // 4: big tok GEMM (ncu profiles this)
    GEMM(feat_tok, D, Wbt, D, 0, big_tok, 2048, bbt, NTOK, 2048);
    // phase-2 composes
    {
        CJob k0 = {Watt, Wbr,           Wbr + 256 * D, 2 * D, 0, D, 0, D};
        CJob k1 = {Watt, Wbe + 256 * D, Wbe + 512 * D, 2 * D, 0, D, 0, D};
        compose_mm_batch<<<dim3(D, 2), D>>>(k0, k1, k0, k0);
        BJob c0 = {Watt, bbe + 256, nullptr, bbe + 512, 2 * D, 0};
        compose_bias_batch<<<dim3(D, 1), D>>>(c0, c0, c0);
    }
    // remaining node GEMMs
    GEMM(feat_srl, D, Wbe, D, 0, a_srl, D, bbe, NSRL, D);
    GEMM(feat_ent, D, Wbe, D, 0, big_ent, 768, bbe, NENT, 768);
    GEMM(bert,     D, Wbr, D, 0, bertW, 512, nullptr, TLEN, 512);

    // CSR builds
    int* cnt_ts = cnt;
    int* cnt_ee = cnt + NSRL;
    int* cnt_st = cnt + NSRL + NENT;
    int* cnt_et = cnt + NSRL + NENT + NTOK;
    fill_int_kernel<<<512, 256>>>(cnt, NSRL + NENT + 2 * NTOK);
    build_csr4_kernel<<<(ETS + EEE + EST + EET + 255) / 256, 256>>>(
        dst_ts, idx_ts, cnt_ts, ETS / NSRL,
        dst_ee, idx_ee, cnt_ee, EEE / NENT,
        dst_st, idx_st, cnt_st, EST / NTOK,
        dst_et, idx_et, cnt_et, EET / NTOK);

    // TS segmented softmax -> h_srl (DEG=15 unrolled)
    seg_softmax_agg_kernel<15><<<NSRL, 256>>>(big_tok + 256, 2048, a_srl, D,
                                              big_tok, 2048, src_ts, idx_ts, h_srl);

    // 512-ch prefix sums -> Q, then fused EE softmax (DEG=15)
    const int nch = (TLEN + CSCH - 1) / CSCH;
    cs_chunk<<<nch, 512>>>(bertW, csum);
    cs_scan<<<2, 256>>>(csum, nch, 512);
    cs_write<<<nch, 512>>>(bertW, csum, Q);
    seg_softmax_ee_kernel<15><<<NENT, 256>>>(Q, span, rel_type, big_ent, src_ee,
                                             idx_ee, h_ent);

    // GRU input projections (h_srl & h_ent contiguous in d_out)
    GEMM(h_srl, D, Wih_r, D, 0, gi, D3, bih, NSRL + NENT, D3);
    float* gi_srl = gi;
    float* gi_ent = gi + (size_t)NSRL * D3;

    // merged edge-GRU aggregation (DEG=6,3 unrolled)
    gru_agg2_kernel<6, 3><<<NTOK, 256>>>(gi_srl, gi_ent, big_tok + 512, 2048, feat_tok,
                                         src_st, idx_st, src_et, idx_et, hst, het);

    GEMM(het, D, Wih_r, D, 0, gA, D3, bih, NTOK, D3);
    GEMM(hst, D, Whh_r, D, 0, gB, D3, bhh, NTOK, D3);
    gru_dense_kernel<<<NTOK, 256>>>(gA, D3, gB, hst, h1);

    GEMM(h1, D, Whh_r, D, 0, gB, D3, bhh, NTOK, D3);
    gru_dense_kernel<<<NTOK, 256>>>(big_tok + 1280, 2048, gB, h1, h_tok);
}